// round 16
// baseline (speedup 1.0000x reference)
#include <cuda_runtime.h>

// RotationGate: batched RX on qubit 0 (MSB axis) of a 22-qubit state.
// state_re/state_im: (DIM, 16) fp32 row-major; each row = 4 float4.
// out: (2, DIM, 16) fp32 (real plane, imag plane).
//   out0 = c*s0 - i*s*s1 ; out1 = c*s1 - i*s*s0  with c=cos(th/2), s=sin(th/2)
//
// FINAL CONVERGED KERNEL (15 measured rounds). HBM-bound streaming with an
// irreducible 1 GiB of traffic (absolute floor ~134us @ 8TB/s spec).
// This exact source measured seven times: total 157.70-158.02us (mean
// 157.80, sigma 0.10), main 149.5-150.8us, 6.76-6.83 TB/s (85-86% spec),
// occ ~82%, issue 12.4% -- pinned at the HBM read/write-turnaround ceiling.
// The ~8us total-main gap is fixed graph-replay overhead outside
// kernel_launch.
//
// Settled by experiment (kept -> mechanism):
//  - single fused kernel: separate prep kernel cost ~5us of graph-node gap.
//  - ZERO synchronization: each thread computes its own 4 (c,s) pairs with
//    MUFU (__cosf/__sinf; args in [0,pi], abs err ~1e-6 << 1e-3 tolerance).
//    A 16-thread+smem+__syncthreads variant gated all stores on warp0: +3-5us.
//  - 1 float4-group per thread: MLP=8/thread raised regs to 43, halving
//    occupancy for zero gain (LSU/L1tex queue binds at the SM level).
//  - tpb=128: finer wave granularity; best DRAM% of {128,256,512}.
//  - plain cached loads AND stores: every .cs-hint combination regressed.
//  - loads in natural order + store-on-ready: consumer-paired load reorder
//    measured main +1.2us -- reverted.
// Ruled out by HW model (no mechanism on the binding resource): LDG.256
// (warp streams already fully line-coalesced; issue not binding), TMA (LTS
// cap path-independent), persistent grid (no tail observed), HBM channel
// striding (hash invisible behind LTS cap on B300).

#define HALF4   8388608    /* (DIM/2)*16/4 float4 per half-plane */
#define IMOFF   16777216   /* DIM*16/4: imag plane offset in float4 */

__global__ __launch_bounds__(128, 16)
void rot_fused_kernel(const float* __restrict__ theta,
                      const float* __restrict__ re_,
                      const float* __restrict__ im_,
                      float* __restrict__ out_) {
    int t = blockIdx.x * 128 + threadIdx.x;   // t in [0, HALF4)
    const float4* __restrict__ re  = (const float4*)re_;
    const float4* __restrict__ im  = (const float4*)im_;
    float4* __restrict__ out = (float4*)out_;

    int g = threadIdx.x & 3;  // batch quad: batches 4g..4g+3
    float4 th = ((const float4*)theta)[g];

    // Front-batch the 4 bulk loads; MUFU coeff math overlaps DRAM latency.
    float4 r0 = re[t];
    float4 i0 = im[t];
    float4 r1 = re[t + HALF4];
    float4 i1 = im[t + HALF4];

    float4 c4, s4;
    c4.x = __cosf(th.x * 0.5f);  s4.x = __sinf(th.x * 0.5f);
    c4.y = __cosf(th.y * 0.5f);  s4.y = __sinf(th.y * 0.5f);
    c4.z = __cosf(th.z * 0.5f);  s4.z = __sinf(th.z * 0.5f);
    c4.w = __cosf(th.w * 0.5f);  s4.w = __sinf(th.w * 0.5f);

    float4 o;

    // Store each result as soon as it is ready.
    o.x = fmaf(c4.x, r0.x,  s4.x * i1.x);
    o.y = fmaf(c4.y, r0.y,  s4.y * i1.y);
    o.z = fmaf(c4.z, r0.z,  s4.z * i1.z);
    o.w = fmaf(c4.w, r0.w,  s4.w * i1.w);
    out[t] = o;

    o.x = fmaf(c4.x, r1.x,  s4.x * i0.x);
    o.y = fmaf(c4.y, r1.y,  s4.y * i0.y);
    o.z = fmaf(c4.z, r1.z,  s4.z * i0.z);
    o.w = fmaf(c4.w, r1.w,  s4.w * i0.w);
    out[t + HALF4] = o;

    o.x = fmaf(c4.x, i0.x, -s4.x * r1.x);
    o.y = fmaf(c4.y, i0.y, -s4.y * r1.y);
    o.z = fmaf(c4.z, i0.z, -s4.z * r1.z);
    o.w = fmaf(c4.w, i0.w, -s4.w * r1.w);
    out[t + IMOFF] = o;

    o.x = fmaf(c4.x, i1.x, -s4.x * r0.x);
    o.y = fmaf(c4.y, i1.y, -s4.y * r0.y);
    o.z = fmaf(c4.z, i1.z, -s4.z * r0.z);
    o.w = fmaf(c4.w, i1.w, -s4.w * r0.w);
    out[t + IMOFF + HALF4] = o;
}

extern "C" void kernel_launch(void* const* d_in, const int* in_sizes, int n_in,
                              void* d_out, int out_size) {
    const float* theta = (const float*)d_in[0];
    const float* s_re  = (const float*)d_in[1];
    const float* s_im  = (const float*)d_in[2];
    float* out = (float*)d_out;

    int tpb    = 128;
    int blocks = HALF4 / tpb;     // 65,536 blocks
    rot_fused_kernel<<<blocks, tpb>>>(theta, s_re, s_im, out);
}

// round 17
// speedup vs baseline: 1.0002x; 1.0002x over previous
#include <cuda_runtime.h>

// RotationGate: batched RX on qubit 0 (MSB axis) of a 22-qubit state.
// state_re/state_im: (DIM, 16) fp32 row-major; each row = 4 float4.
// out: (2, DIM, 16) fp32 (real plane, imag plane).
//   out0 = c*s0 - i*s*s1 ; out1 = c*s1 - i*s*s0  with c=cos(th/2), s=sin(th/2)
//
// FINAL CONVERGED KERNEL (16 measured rounds). HBM-bound streaming with an
// irreducible 1 GiB of traffic (absolute floor ~134us @ 8TB/s spec).
// This exact source measured eight times: total 157.70-158.02us (mean
// 157.80, sigma 0.09), main 149.5-151.6us, 6.73-6.83 TB/s (84-86% spec),
// occ ~82%, issue 12.4% -- pinned at the HBM read/write-turnaround ceiling.
// The ~8us total-main gap is fixed graph-replay overhead outside
// kernel_launch.
//
// Settled by experiment (kept -> mechanism):
//  - single fused kernel: separate prep kernel cost ~5us of graph-node gap.
//  - ZERO synchronization: each thread computes its own 4 (c,s) pairs with
//    MUFU (__cosf/__sinf; args in [0,pi], abs err ~1e-6 << 1e-3 tolerance).
//    A 16-thread+smem+__syncthreads variant gated all stores on warp0: +3-5us.
//  - 1 float4-group per thread: MLP=8/thread raised regs to 43, halving
//    occupancy for zero gain (LSU/L1tex queue binds at the SM level).
//  - tpb=128: finer wave granularity; best DRAM% of {128,256,512}.
//  - plain cached loads AND stores: every .cs-hint combination regressed.
//  - loads in natural order + store-on-ready: consumer-paired load reorder
//    measured main +1.2us -- reverted.
// Ruled out by HW model (no mechanism on the binding resource): LDG.256
// (warp streams already fully line-coalesced; issue not binding), TMA (LTS
// cap path-independent), persistent grid (no tail observed), HBM channel
// striding (hash invisible behind LTS cap on B300).

#define HALF4   8388608    /* (DIM/2)*16/4 float4 per half-plane */
#define IMOFF   16777216   /* DIM*16/4: imag plane offset in float4 */

__global__ __launch_bounds__(128, 16)
void rot_fused_kernel(const float* __restrict__ theta,
                      const float* __restrict__ re_,
                      const float* __restrict__ im_,
                      float* __restrict__ out_) {
    int t = blockIdx.x * 128 + threadIdx.x;   // t in [0, HALF4)
    const float4* __restrict__ re  = (const float4*)re_;
    const float4* __restrict__ im  = (const float4*)im_;
    float4* __restrict__ out = (float4*)out_;

    int g = threadIdx.x & 3;  // batch quad: batches 4g..4g+3
    float4 th = ((const float4*)theta)[g];

    // Front-batch the 4 bulk loads; MUFU coeff math overlaps DRAM latency.
    float4 r0 = re[t];
    float4 i0 = im[t];
    float4 r1 = re[t + HALF4];
    float4 i1 = im[t + HALF4];

    float4 c4, s4;
    c4.x = __cosf(th.x * 0.5f);  s4.x = __sinf(th.x * 0.5f);
    c4.y = __cosf(th.y * 0.5f);  s4.y = __sinf(th.y * 0.5f);
    c4.z = __cosf(th.z * 0.5f);  s4.z = __sinf(th.z * 0.5f);
    c4.w = __cosf(th.w * 0.5f);  s4.w = __sinf(th.w * 0.5f);

    float4 o;

    // Store each result as soon as it is ready.
    o.x = fmaf(c4.x, r0.x,  s4.x * i1.x);
    o.y = fmaf(c4.y, r0.y,  s4.y * i1.y);
    o.z = fmaf(c4.z, r0.z,  s4.z * i1.z);
    o.w = fmaf(c4.w, r0.w,  s4.w * i1.w);
    out[t] = o;

    o.x = fmaf(c4.x, r1.x,  s4.x * i0.x);
    o.y = fmaf(c4.y, r1.y,  s4.y * i0.y);
    o.z = fmaf(c4.z, r1.z,  s4.z * i0.z);
    o.w = fmaf(c4.w, r1.w,  s4.w * i0.w);
    out[t + HALF4] = o;

    o.x = fmaf(c4.x, i0.x, -s4.x * r1.x);
    o.y = fmaf(c4.y, i0.y, -s4.y * r1.y);
    o.z = fmaf(c4.z, i0.z, -s4.z * r1.z);
    o.w = fmaf(c4.w, i0.w, -s4.w * r1.w);
    out[t + IMOFF] = o;

    o.x = fmaf(c4.x, i1.x, -s4.x * r0.x);
    o.y = fmaf(c4.y, i1.y, -s4.y * r0.y);
    o.z = fmaf(c4.z, i1.z, -s4.z * r0.z);
    o.w = fmaf(c4.w, i1.w, -s4.w * r0.w);
    out[t + IMOFF + HALF4] = o;
}

extern "C" void kernel_launch(void* const* d_in, const int* in_sizes, int n_in,
                              void* d_out, int out_size) {
    const float* theta = (const float*)d_in[0];
    const float* s_re  = (const float*)d_in[1];
    const float* s_im  = (const float*)d_in[2];
    float* out = (float*)d_out;

    int tpb    = 128;
    int blocks = HALF4 / tpb;     // 65,536 blocks
    rot_fused_kernel<<<blocks, tpb>>>(theta, s_re, s_im, out);
}